// round 2
// baseline (speedup 1.0000x reference)
#include <cuda_runtime.h>

#define DIM 1024
#define HEADS 16
#define DHEAD 64
#define BATCH 2
#define SEQ 2048
#define TOKENS (BATCH*SEQ)   // 4096
#define QKV_N (3*DIM)        // 3072

// ---------------- scratch (device globals: no allocations allowed) ------------
__device__ float g_xn[TOKENS*DIM];                 // normalized input
__device__ float g_q[BATCH*HEADS*SEQ*DHEAD];       // [bh, n, dh]
__device__ float g_k[BATCH*HEADS*SEQ*DHEAD];
__device__ float g_v[BATCH*HEADS*SEQ*DHEAD];
__device__ float g_gates[TOKENS*HEADS];            // sigmoid(g) per (t, h)
__device__ float g_merged[TOKENS*DIM];             // gated attn out, merged heads
__device__ float g_rope[SEQ*DHEAD];                // [pos][p*2 + {cos,sin}], p<32

// ---------------- RoPE table --------------------------------------------------
__global__ void rope_table_kernel(const float* __restrict__ freqs) {
    int idx = blockIdx.x * blockDim.x + threadIdx.x;  // SEQ*32 entries
    if (idx >= SEQ * 32) return;
    int pos = idx >> 5, p = idx & 31;
    float f = (float)pos * freqs[p];
    g_rope[pos*64 + p*2 + 0] = cosf(f);
    g_rope[pos*64 + p*2 + 1] = sinf(f);
}

// ---------------- RMSNorm (L2-norm variant) -----------------------------------
__global__ __launch_bounds__(256) void rmsnorm_kernel(const float* __restrict__ x,
                                                      const float* __restrict__ gamma) {
    int t = blockIdx.x;
    int tid = threadIdx.x;                    // 256 threads, 4 floats each = 1024
    const float4* xr = (const float4*)(x + (size_t)t * DIM);
    float4 v = xr[tid];
    float ss = v.x*v.x + v.y*v.y + v.z*v.z + v.w*v.w;
    __shared__ float red[8];
    #pragma unroll
    for (int o = 16; o; o >>= 1) ss += __shfl_down_sync(0xffffffffu, ss, o);
    if ((tid & 31) == 0) red[tid >> 5] = ss;
    __syncthreads();
    __shared__ float bscale;
    if (tid == 0) {
        float s = 0.f;
        #pragma unroll
        for (int i = 0; i < 8; i++) s += red[i];
        bscale = 32.0f * rsqrtf(s);           // sqrt(1024)/||x||
    }
    __syncthreads();
    float sc = bscale;
    float4 g = ((const float4*)gamma)[tid];
    float4 o;
    o.x = v.x * sc * g.x; o.y = v.y * sc * g.y;
    o.z = v.z * sc * g.z; o.w = v.w * sc * g.w;
    ((float4*)(g_xn + (size_t)t * DIM))[tid] = o;
}

// ---------------- gates: sigmoid(xn @ w_gates + b) ----------------------------
__global__ __launch_bounds__(512) void gates_kernel(const float* __restrict__ wg,
                                                    const float* __restrict__ bg) {
    int t = blockIdx.x;
    int h = threadIdx.x >> 5;                 // 16 warps, one head each
    int lane = threadIdx.x & 31;
    const float* xr = g_xn + (size_t)t * DIM;
    float s = 0.f;
    #pragma unroll 8
    for (int k = lane; k < DIM; k += 32)
        s += xr[k] * wg[k * HEADS + h];
    #pragma unroll
    for (int o = 16; o; o >>= 1) s += __shfl_down_sync(0xffffffffu, s, o);
    if (lane == 0) {
        float z = s + bg[h];
        g_gates[t * HEADS + h] = 1.f / (1.f + __expf(-z));
    }
}

// ---------------- tiled SGEMM, 128x128x8, 256 threads, 8x8/thread -------------
// MODE 0: A = g_xn (4096x1024), B = w_qkv (1024x3072); epilogue applies RoPE
//         and scatters into g_q/g_k/g_v [bh, n, dh].
// MODE 1: A = g_merged (4096x1024), B = w_out (1024x1024); plain store to C.
template<int MODE>
__global__ __launch_bounds__(256) void sgemm_kernel(const float* __restrict__ B,
                                                    float* __restrict__ C) {
    const int N = (MODE == 0) ? QKV_N : DIM;
    const int K = DIM;
    const float* A = (MODE == 0) ? g_xn : g_merged;

    __shared__ float As[8][128];
    __shared__ float Bs[8][128];
    int tid = threadIdx.x;
    int a_row = tid >> 1, a_col = (tid & 1) * 4;
    int b_row = tid >> 5, b_col = (tid & 31) * 4;
    int tx = tid & 15, ty = tid >> 4;

    const float* Ab = A + (size_t)(blockIdx.y * 128) * K;
    const float* Bb = B + blockIdx.x * 128;

    float acc[8][8];
    #pragma unroll
    for (int i = 0; i < 8; i++)
        #pragma unroll
        for (int j = 0; j < 8; j++) acc[i][j] = 0.f;

    for (int k0 = 0; k0 < K; k0 += 8) {
        float4 av = *(const float4*)(Ab + (size_t)a_row * K + k0 + a_col);
        As[a_col + 0][a_row] = av.x;
        As[a_col + 1][a_row] = av.y;
        As[a_col + 2][a_row] = av.z;
        As[a_col + 3][a_row] = av.w;
        *(float4*)&Bs[b_row][b_col] = *(const float4*)(Bb + (size_t)(k0 + b_row) * N + b_col);
        __syncthreads();
        #pragma unroll
        for (int kk = 0; kk < 8; kk++) {
            float4 a0 = *(const float4*)&As[kk][ty * 4];
            float4 a1 = *(const float4*)&As[kk][64 + ty * 4];
            float4 b0 = *(const float4*)&Bs[kk][tx * 4];
            float4 b1 = *(const float4*)&Bs[kk][64 + tx * 4];
            float ar[8] = {a0.x, a0.y, a0.z, a0.w, a1.x, a1.y, a1.z, a1.w};
            float br[8] = {b0.x, b0.y, b0.z, b0.w, b1.x, b1.y, b1.z, b1.w};
            #pragma unroll
            for (int i = 0; i < 8; i++)
                #pragma unroll
                for (int j = 0; j < 8; j++)
                    acc[i][j] += ar[i] * br[j];
        }
        __syncthreads();
    }

    #pragma unroll
    for (int ri = 0; ri < 2; ri++) {
        #pragma unroll
        for (int i = 0; i < 4; i++) {
            int r = ri * 64 + ty * 4 + i;
            int t = blockIdx.y * 128 + r;
            #pragma unroll
            for (int rj = 0; rj < 2; rj++) {
                int c = blockIdx.x * 128 + rj * 64 + tx * 4;
                float v0 = acc[ri*4+i][rj*4+0], v1 = acc[ri*4+i][rj*4+1];
                float v2 = acc[ri*4+i][rj*4+2], v3 = acc[ri*4+i][rj*4+3];
                if (MODE == 1) {
                    *(float4*)(C + (size_t)t * N + c) = make_float4(v0, v1, v2, v3);
                } else {
                    int b = t >> 11, pos = t & (SEQ - 1);
                    int s = c >> 10;            // 0=q, 1=k, 2=v
                    int rem = c & 1023;
                    int h = rem >> 6;
                    int dd = rem & 63;
                    float4 o;
                    if (s < 2) {
                        const float* rp = g_rope + pos * 64 + (dd >> 1) * 2;
                        float c0 = rp[0], s0 = rp[1], c1 = rp[2], s1 = rp[3];
                        o.x = v0 * c0 - v1 * s0;
                        o.y = v1 * c0 + v0 * s0;
                        o.z = v2 * c1 - v3 * s1;
                        o.w = v3 * c1 + v2 * s1;
                    } else {
                        o = make_float4(v0, v1, v2, v3);
                    }
                    float* dst = (s == 0) ? g_q : ((s == 1) ? g_k : g_v);
                    *(float4*)(dst + ((size_t)(b * HEADS + h) * SEQ + pos) * DHEAD + dd) = o;
                }
            }
        }
    }
}

// ---------------- flash attention + fused sigmoid gate ------------------------
// grid: (SEQ/128, BATCH*HEADS), block 128. One q row per thread, 64-key tiles.
// Branch-free online softmax: per-key rescale with fmaxf-based new max.
__global__ __launch_bounds__(128) void attn_kernel() {
    __shared__ float4 Ks[64 * 16];
    __shared__ float4 Vs[64 * 16];
    int bh = blockIdx.y;
    int b = bh >> 4, h = bh & 15;
    int qrow = blockIdx.x * 128 + threadIdx.x;

    const float4* qp = (const float4*)(g_q + ((size_t)bh * SEQ + qrow) * DHEAD);
    float4 q[16];
    #pragma unroll
    for (int i = 0; i < 16; i++) q[i] = qp[i];

    float4 acc[16];
    #pragma unroll
    for (int i = 0; i < 16; i++) acc[i] = make_float4(0.f, 0.f, 0.f, 0.f);
    float m = -1e30f, l = 0.f;

    for (int kt = 0; kt < SEQ; kt += 64) {
        const float4* kb = (const float4*)(g_k + ((size_t)bh * SEQ + kt) * DHEAD);
        const float4* vb = (const float4*)(g_v + ((size_t)bh * SEQ + kt) * DHEAD);
        #pragma unroll
        for (int i = 0; i < 8; i++) {
            Ks[threadIdx.x + i * 128] = kb[threadIdx.x + i * 128];
            Vs[threadIdx.x + i * 128] = vb[threadIdx.x + i * 128];
        }
        __syncthreads();

        // tile-local max pass: compute scores for this tile into registers is
        // too big; instead do per-key branch-free online update.
        #pragma unroll 2
        for (int j = 0; j < 64; j++) {
            const float4* kr = &Ks[j * 16];
            float s = 0.f;
            #pragma unroll
            for (int d = 0; d < 16; d++) {
                float4 kv = kr[d];
                s += q[d].x*kv.x + q[d].y*kv.y + q[d].z*kv.z + q[d].w*kv.w;
            }
            s *= 0.125f;                       // dh^-0.5
            float mn = fmaxf(m, s);
            float corr = __expf(m - mn);       // 1 when m unchanged
            float p = __expf(s - mn);
            m = mn;
            l = l * corr + p;
            const float4* vr = &Vs[j * 16];
            #pragma unroll
            for (int d = 0; d < 16; d++) {
                float4 vv = vr[d];
                acc[d].x = acc[d].x * corr + p * vv.x;
                acc[d].y = acc[d].y * corr + p * vv.y;
                acc[d].z = acc[d].z * corr + p * vv.z;
                acc[d].w = acc[d].w * corr + p * vv.w;
            }
        }
        __syncthreads();
    }

    int t = b * SEQ + qrow;
    float gate = g_gates[t * HEADS + h];
    float inv = gate / l;
    float4* op = (float4*)(g_merged + (size_t)t * DIM + h * DHEAD);
    #pragma unroll
    for (int d = 0; d < 16; d++) {
        float4 o;
        o.x = acc[d].x * inv; o.y = acc[d].y * inv;
        o.z = acc[d].z * inv; o.w = acc[d].w * inv;
        op[d] = o;
    }
}

// ---------------- launch ------------------------------------------------------
extern "C" void kernel_launch(void* const* d_in, const int* in_sizes, int n_in,
                              void* d_out, int out_size) {
    const float* x       = (const float*)d_in[0];
    const float* gamma   = (const float*)d_in[1];
    const float* w_qkv   = (const float*)d_in[2];
    const float* w_gates = (const float*)d_in[3];
    const float* b_gates = (const float*)d_in[4];
    const float* w_out   = (const float*)d_in[5];
    const float* freqs   = (const float*)d_in[6];
    float* out = (float*)d_out;

    rope_table_kernel<<<(SEQ * 32 + 255) / 256, 256>>>(freqs);
    rmsnorm_kernel<<<TOKENS, 256>>>(x, gamma);
    gates_kernel<<<TOKENS, 512>>>(w_gates, b_gates);
    {
        dim3 grid(QKV_N / 128, TOKENS / 128);
        sgemm_kernel<0><<<grid, 256>>>(w_qkv, nullptr);
    }
    {
        dim3 grid(SEQ / 128, BATCH * HEADS);
        attn_kernel<<<grid, 128>>>();
    }
    {
        dim3 grid(DIM / 128, TOKENS / 128);
        sgemm_kernel<1><<<grid, 256>>>(w_out, out);
    }
}